// round 14
// baseline (speedup 1.0000x reference)
#include <cuda_runtime.h>
#include <cuda_pipeline.h>
#include <cstdint>

typedef unsigned long long u64;

#define BB 2
#define CC 256
#define RR 32
#define NN 6272
#define NT 49
#define JS 3

#define PS 68                  // O-staging row stride (floats)
#define KVBUF_U 4608           // u32 per KV buffer: kh1280+kl1280+vh1024+vl1024
#define FL_SMEM_BYTES (2 * KVBUF_U * 4)   // 36864; O staging aliases KV buffers

// ---------------- scratch ---------------------------------------------------
__device__ uint32_t g_qbh[BB][NN][16];  // q bf16-hi pairs (r=2u,2u+1), natural
__device__ uint32_t g_qbl[BB][NN][16];  // q bf16-lo pairs
__device__ uint32_t g_kbh[BB][NN][16];  // k bf16-hi pairs, slot-permuted
__device__ uint32_t g_kbl[BB][NN][16];
__device__ uint32_t g_vbh[BB][RR][NN/2]; // v bf16-hi pairs [r][perm j-pair]
__device__ uint32_t g_vbl[BB][RR][NN/2];
__device__ float    g_op [BB*JS][RR][NN];
__device__ float    g_ll [BB*JS][NN];

// ---------------- helpers ----------------------------------------------------
__device__ __forceinline__ u64 dup2(float a) {
    u64 r; asm("mov.b64 %0,{%1,%1};" : "=l"(r) : "f"(a)); return r;
}
__device__ __forceinline__ u64 ffma2(u64 a, u64 b, u64 c) {
    u64 d; asm("fma.rn.f32x2 %0,%1,%2,%3;" : "=l"(d) : "l"(a), "l"(b), "l"(c)); return d;
}
__device__ __forceinline__ void unpack2(u64 a, float& x, float& y) {
    asm("mov.b64 {%0,%1},%2;" : "=f"(x), "=f"(y) : "l"(a));
}
__device__ __forceinline__ float ex2(float x) {
    float y; asm("ex2.approx.f32 %0,%1;" : "=f"(y) : "f"(x)); return y;
}
__device__ __forceinline__ uint32_t bfpack(float v0, float v1) {
    uint32_t r;
    asm("cvt.rn.bf16x2.f32 %0, %1, %2;" : "=r"(r) : "f"(v1), "f"(v0));
    return r;
}
__device__ __forceinline__ void bfsplit(float v0, float v1,
                                        uint32_t& hp, uint32_t& lp) {
    hp = bfpack(v0, v1);
    float h0 = __uint_as_float(hp << 16);
    float h1 = __uint_as_float(hp & 0xffff0000u);
    lp = bfpack(v0 - h0, v1 - h1);
}
__device__ __forceinline__ void mma16(float* c, const uint32_t* a,
                                      uint32_t b0, uint32_t b1) {
    asm("mma.sync.aligned.m16n8k16.row.col.f32.bf16.bf16.f32 "
        "{%0,%1,%2,%3}, {%4,%5,%6,%7}, {%8,%9}, {%0,%1,%2,%3};"
        : "+f"(c[0]), "+f"(c[1]), "+f"(c[2]), "+f"(c[3])
        : "r"(a[0]), "r"(a[1]), "r"(a[2]), "r"(a[3]), "r"(b0), "r"(b1));
}

// ============================================================================
// Kernel 1: projection, one of {q,k,v} per block. grid (49, 3, 2), 256 thr.
// 32-channel double-buffered x chunks (64 KB smem total -> 2-3 CTAs/SM).
// ============================================================================
#define PROJ_SMEM_FLOATS (8192 + 2 * 4096)
#define PROJ_SMEM_BYTES  (PROJ_SMEM_FLOATS * 4)   // 65536

__global__ void __launch_bounds__(256) proj_kernel(
    const float* __restrict__ x, const float* __restrict__ qw,
    const float* __restrict__ kw, const float* __restrict__ vw)
{
    extern __shared__ float sm[];
    float* ws = sm;           // [32][256] weights; reused as V staging
    float* xs = sm + 8192;    // 2 x [32][128]
    int tid = threadIdx.x, nt = blockIdx.x, which = blockIdx.y, b = blockIdx.z;
    const float* w = (which == 0) ? qw : (which == 1) ? kw : vw;
    const float* xb = x + (size_t)b * CC * NN + nt * 128;

    #pragma unroll
    for (int i = 0; i < 8; i++)
        __pipeline_memcpy_async(&ws[(tid + i * 256) * 4], &w[(tid + i * 256) * 4], 16);
    #pragma unroll
    for (int i = 0; i < 4; i++) {
        int lin4 = tid + i * 256;
        int cc = lin4 >> 5, nn4 = (lin4 & 31) * 4;
        __pipeline_memcpy_async(&xs[cc * 128 + nn4],
                                &xb[(size_t)cc * NN + nn4], 16);
    }
    __pipeline_commit();

    int tr = tid >> 5, tn = tid & 31;
    u64 acc[4][2];
    #pragma unroll
    for (int i = 0; i < 4; i++) { acc[i][0] = 0ull; acc[i][1] = 0ull; }

    #pragma unroll
    for (int ch = 0; ch < 8; ch++) {
        __pipeline_wait_prior(0);
        __syncthreads();
        if (ch + 1 < 8) {
            float* xd = xs + ((ch + 1) & 1) * 4096;
            int c0n = (ch + 1) * 32;
            #pragma unroll
            for (int i = 0; i < 4; i++) {
                int lin4 = tid + i * 256;
                int cc = lin4 >> 5, nn4 = (lin4 & 31) * 4;
                __pipeline_memcpy_async(&xd[cc * 128 + nn4],
                                        &xb[(size_t)(c0n + cc) * NN + nn4], 16);
            }
            __pipeline_commit();
        }
        float* xc = xs + (ch & 1) * 4096;
        int c0 = ch * 32;
        #pragma unroll 8
        for (int cc = 0; cc < 32; cc++) {
            ulonglong2 xv = *(ulonglong2*)&xc[cc * 128 + tn * 4];
            #pragma unroll
            for (int rr = 0; rr < 4; rr++) {
                u64 wv = dup2(ws[(tr * 4 + rr) * 256 + c0 + cc]);
                acc[rr][0] = ffma2(wv, xv.x, acc[rr][0]);
                acc[rr][1] = ffma2(wv, xv.y, acc[rr][1]);
            }
        }
    }

    const float qscale = 0.17677669529663687f * 1.4426950408889634f;
    int n0 = nt * 128 + tn * 4, r0 = tr * 4;
    float vals[4][4];   // [rr][nn]
    #pragma unroll
    for (int rr = 0; rr < 4; rr++) {
        unpack2(acc[rr][0], vals[rr][0], vals[rr][1]);
        unpack2(acc[rr][1], vals[rr][2], vals[rr][3]);
    }

    if (which == 0) {
        #pragma unroll
        for (int nn = 0; nn < 4; nn++) {
            uint32_t hp0, lp0, hp1, lp1;
            bfsplit(vals[0][nn] * qscale, vals[1][nn] * qscale, hp0, lp0);
            bfsplit(vals[2][nn] * qscale, vals[3][nn] * qscale, hp1, lp1);
            *(uint2*)&g_qbh[b][n0 + nn][2 * tr] = make_uint2(hp0, hp1);
            *(uint2*)&g_qbl[b][n0 + nn][2 * tr] = make_uint2(lp0, lp1);
        }
    } else if (which == 1) {
        // K: slot-permuted: u -> p = kts*8 + 2*(w&3) + (w>>2)
        #pragma unroll
        for (int nn = 0; nn < 4; nn++) {
            #pragma unroll
            for (int pi = 0; pi < 2; pi++) {
                uint32_t hp, lp;
                bfsplit(vals[2 * pi][nn], vals[2 * pi + 1][nn], hp, lp);
                int u = 2 * tr + pi;
                int kts = u >> 3, ww = u & 7;
                int p = kts * 8 + 2 * (ww & 3) + (ww >> 2);
                g_kbh[b][n0 + nn][p] = hp;
                g_kbl[b][n0 + nn][p] = lp;
            }
        }
    } else {
        // V: bf16 hi/lo pairs along j, permuted slot layout per 64-j tile.
        __syncthreads();
        uint32_t* st_h = (uint32_t*)ws;          // [32 r][64 u32]
        uint32_t* st_l = (uint32_t*)ws + 2048;
        #pragma unroll
        for (int rr = 0; rr < 4; rr++) {
            #pragma unroll
            for (int pi = 0; pi < 2; pi++) {
                uint32_t hp, lp;
                bfsplit(vals[rr][2 * pi], vals[rr][2 * pi + 1], hp, lp);
                int ulc = tn * 2 + pi;
                int tl = ulc >> 5, ul = ulc & 31;
                int kt = ul >> 3, ww = ul & 7;
                int idx = tl * 32 + 2 * (kt * 4 + (ww & 3)) + (ww >> 2);
                st_h[(r0 + rr) * 64 + idx] = hp;
                st_l[(r0 + rr) * 64 + idx] = lp;
            }
        }
        __syncthreads();
        #pragma unroll
        for (int i = 0; i < 2; i++) {
            int lin4 = tid + i * 256;
            int r = lin4 >> 4, c4 = (lin4 & 15) * 4;
            *(uint4*)&g_vbh[b][r][nt * 64 + c4] = *(uint4*)&st_h[r * 64 + c4];
            *(uint4*)&g_vbl[b][r][nt * 64 + c4] = *(uint4*)&st_l[r * 64 + c4];
        }
    }
}

// ============================================================================
// Kernel 2: flash. grid (49, 3, 2), 256 threads (8 warps).
// S: bf16 m16n8k16 3-term (48 mma). Softmax+PV interleaved per kt-step so
// MUFU/pack of step kt+1 issue under the tensor phase of step kt.
// O staging aliases the KV buffers in the epilogue.
// ============================================================================
__device__ __forceinline__ void load_kv(uint32_t* smbase, int buf, int b,
                                        int j0, int tid)
{
    uint32_t* kd = smbase + buf * KVBUF_U;
    uint32_t* kld = kd + 1280;
    uint32_t* vhd = kd + 2560;
    uint32_t* vld = kd + 3584;
    #pragma unroll
    for (int i = 0; i < 2; i++) {
        int c = tid + i * 256;              // 0..511
        int arr = c >> 8, cc = c & 255;
        int j = cc >> 2, uu = cc & 3;
        uint32_t* dst = (arr ? kld : kd) + j * 20 + uu * 4;
        const uint32_t* src = arr ? &g_kbl[b][j0 + j][uu * 4]
                                  : &g_kbh[b][j0 + j][uu * 4];
        __pipeline_memcpy_async(dst, src, 16);
    }
    int jp0 = j0 >> 1;
    #pragma unroll
    for (int i = 0; i < 2; i++) {
        int c = tid + i * 256;              // 0..511
        int arr = c >> 8, cc = c & 255;
        int r = cc >> 3, ch = cc & 7;
        uint32_t off = (uint32_t)(r * 32 + ((4 * ch) ^ ((r & 3) << 3)));
        uint32_t* dst = (arr ? vld : vhd) + off;
        const uint32_t* src = arr ? &g_vbl[b][r][jp0 + 4 * ch]
                                  : &g_vbh[b][r][jp0 + 4 * ch];
        __pipeline_memcpy_async(dst, src, 16);
    }
    __pipeline_commit();
}

__global__ void __launch_bounds__(256, 2) flash_kernel()
{
    extern __shared__ float sm[];
    uint32_t* smu = (uint32_t*)sm;
    int tid = threadIdx.x;
    int w = tid >> 5, ln = tid & 31;
    int g = ln >> 2, t = ln & 3;

    int it = blockIdx.x, spl = blockIdx.y, b = blockIdx.z;
    int i0 = it * 128;
    int jt0 = spl * 33;
    int njt = (spl < 2) ? 33 : 32;
    int iw = i0 + w * 16;

    load_kv(smu, 0, b, jt0 * 64, tid);

    uint32_t qAh[2][4], qAl[2][4];
    {
        const uint32_t* qh = &g_qbh[b][0][0];
        const uint32_t* ql = &g_qbl[b][0][0];
        #pragma unroll
        for (int kts = 0; kts < 2; kts++) {
            int cA = kts * 8 + t, cB = kts * 8 + t + 4;
            qAh[kts][0] = qh[(size_t)(iw + g) * 16 + cA];
            qAh[kts][1] = qh[(size_t)(iw + g + 8) * 16 + cA];
            qAh[kts][2] = qh[(size_t)(iw + g) * 16 + cB];
            qAh[kts][3] = qh[(size_t)(iw + g + 8) * 16 + cB];
            qAl[kts][0] = ql[(size_t)(iw + g) * 16 + cA];
            qAl[kts][1] = ql[(size_t)(iw + g + 8) * 16 + cA];
            qAl[kts][2] = ql[(size_t)(iw + g) * 16 + cB];
            qAl[kts][3] = ql[(size_t)(iw + g + 8) * 16 + cB];
        }
    }

    float oC[4][4];
    #pragma unroll
    for (int i = 0; i < 4; i++)
        #pragma unroll
        for (int j = 0; j < 4; j++) oC[i][j] = 0.0f;
    float oL[4] = {0.0f, 0.0f, 0.0f, 0.0f};

    const uint32_t ONE2 = 0x3f803f80u;   // bf16x2 (1.0, 1.0)

    for (int jt = 0; jt < njt; jt++) {
        int buf = jt & 1;
        __pipeline_wait_prior(0);
        __syncthreads();
        if (jt + 1 < njt) load_kv(smu, buf ^ 1, b, (jt0 + jt + 1) * 64, tid);

        const uint32_t* khs = smu + buf * KVBUF_U;
        const uint32_t* kls = khs + 1280;
        const uint32_t* vhs = khs + 2560;
        const uint32_t* vls = khs + 3584;

        // ---- S = Q K^T : bf16 3-term, accumulators pre-biased to -64 --------
        float sC[8][4];
        #pragma unroll
        for (int nt = 0; nt < 8; nt++)
            #pragma unroll
            for (int r = 0; r < 4; r++) sC[nt][r] = -64.0f;

        #pragma unroll
        for (int kts = 0; kts < 2; kts++)
            #pragma unroll
            for (int nt = 0; nt < 8; nt++) {
                int off = (nt * 8 + g) * 20 + 2 * (kts * 4 + t);
                uint2 hh = *(const uint2*)&khs[off];
                uint2 ll = *(const uint2*)&kls[off];
                mma16(sC[nt], qAh[kts], hh.x, hh.y);
                mma16(sC[nt], qAh[kts], ll.x, ll.y);
                mma16(sC[nt], qAl[kts], hh.x, hh.y);
            }

        // ---- softmax + PV interleaved per kt (MUFU overlaps tensor) ---------
        #pragma unroll
        for (int kt = 0; kt < 4; kt++) {
            float e0 = ex2(sC[2 * kt][0]);
            float e1 = ex2(sC[2 * kt][1]);
            float e2 = ex2(sC[2 * kt][2]);
            float e3 = ex2(sC[2 * kt][3]);
            float e4 = ex2(sC[2 * kt + 1][0]);
            float e5 = ex2(sC[2 * kt + 1][1]);
            float e6 = ex2(sC[2 * kt + 1][2]);
            float e7 = ex2(sC[2 * kt + 1][3]);
            uint32_t pA[4];
            pA[0] = bfpack(e0, e1);
            pA[1] = bfpack(e2, e3);
            pA[2] = bfpack(e4, e5);
            pA[3] = bfpack(e6, e7);
            #pragma unroll
            for (int nt2 = 0; nt2 < 4; nt2++) {
                int r = nt2 * 8 + g;
                uint32_t off = (uint32_t)(r * 32 +
                               2 * ((kt * 4 + t) ^ ((r & 3) << 2)));
                uint2 vh2 = *(const uint2*)&vhs[off];
                uint2 vl2 = *(const uint2*)&vls[off];
                mma16(oC[nt2], pA, vh2.x, vh2.y);
                mma16(oC[nt2], pA, vl2.x, vl2.y);
            }
            mma16(oL, pA, ONE2, ONE2);
        }
    }

    // ---- epilogue: O staging aliases the dead KV buffers --------------------
    __syncthreads();      // all warps done reading KV smem
    int bs = b * JS + spl;
    float* pw = sm + w * (16 * PS);
    #pragma unroll
    for (int nt = 0; nt < 4; nt++) {
        *(float2*)&pw[g * PS + nt * 8 + 2 * t]       = make_float2(oC[nt][0], oC[nt][1]);
        *(float2*)&pw[(g + 8) * PS + nt * 8 + 2 * t] = make_float2(oC[nt][2], oC[nt][3]);
    }
    if (t == 0) {
        g_ll[bs][iw + g]     = oL[0];
        g_ll[bs][iw + g + 8] = oL[2];
    }
    __syncthreads();
    #pragma unroll
    for (int i = 0; i < 16; i++) {
        int idx = tid + i * 256;          // 0..4095
        int r = idx >> 7, ii = idx & 127;
        int w2 = ii >> 4, il = ii & 15;
        g_op[bs][r][i0 + ii] = sm[w2 * (16 * PS) + il * PS + r];
    }
}

// ============================================================================
// Kernel 3: split combine + output projection + residual. grid (49, 2)
// ============================================================================
#define K3_SMEM_FLOATS (4096 + 8192 + 128 + 32768)
#define K3_SMEM_BYTES  (K3_SMEM_FLOATS * 4)

__global__ void __launch_bounds__(256) combine_kernel(
    const float* __restrict__ x, const float* __restrict__ ow,
    float* __restrict__ out)
{
    extern __shared__ float sm[];
    float* oc  = sm;            // [32][128]
    float* ows = sm + 4096;     // [256][32]
    float* inv = sm + 12288;    // [128]
    float* os  = sm + 12416;    // [256][128]

    int tid = threadIdx.x, nt = blockIdx.x, b = blockIdx.y;
    int n0 = nt * 128;

    #pragma unroll
    for (int i = 0; i < 8; i++) {
        int lin4 = tid + i * 256;
        *(float4*)&ows[lin4 * 4] = *(const float4*)&ow[lin4 * 4];
    }
    if (tid < 128) {
        int n = n0 + tid;
        inv[tid] = 1.0f / (g_ll[b*3+0][n] + g_ll[b*3+1][n] + g_ll[b*3+2][n]);
    }
    __syncthreads();

    #pragma unroll
    for (int i = 0; i < 16; i++) {
        int idx = tid + i * 256;
        int r = idx >> 7, n = idx & 127;
        oc[idx] = (g_op[b*3+0][r][n0+n] + g_op[b*3+1][r][n0+n]
                 + g_op[b*3+2][r][n0+n]) * inv[n];
    }
    __syncthreads();

    {
        u64 wd[32];
        #pragma unroll
        for (int r = 0; r < 32; r++) wd[r] = dup2(ows[tid * 32 + r]);
        #pragma unroll 2
        for (int np = 0; np < 64; np++) {
            u64 acc = 0ull;
            #pragma unroll
            for (int r = 0; r < 32; r++)
                acc = ffma2(wd[r], *(u64*)&oc[r * 128 + np * 2], acc);
            *(u64*)&os[tid * 128 + np * 2] = acc;
        }
    }
    __syncthreads();

    const float* xb = x + (size_t)b * CC * NN;
    float* ob = out + (size_t)b * CC * NN;
    #pragma unroll
    for (int i = 0; i < 32; i++) {
        int lin4 = tid + i * 256;
        int c = lin4 >> 5, n4 = (lin4 & 31) * 4;
        float4 xv = *(const float4*)&xb[(size_t)c * NN + n0 + n4];
        float4 ov = *(float4*)&os[c * 128 + n4];
        *(float4*)&ob[(size_t)c * NN + n0 + n4] =
            make_float4(xv.x + ov.x, xv.y + ov.y, xv.z + ov.z, xv.w + ov.w);
    }
}

// ============================================================================
extern "C" void kernel_launch(void* const* d_in, const int* in_sizes, int n_in,
                              void* d_out, int out_size)
{
    const float* x  = (const float*)d_in[0];
    const float* qw = (const float*)d_in[1];
    const float* kw = (const float*)d_in[2];
    const float* vw = (const float*)d_in[3];
    const float* ow = (const float*)d_in[4];
    float* out = (float*)d_out;

    cudaFuncSetAttribute(proj_kernel,
        cudaFuncAttributeMaxDynamicSharedMemorySize, PROJ_SMEM_BYTES);
    cudaFuncSetAttribute(flash_kernel,
        cudaFuncAttributeMaxDynamicSharedMemorySize, FL_SMEM_BYTES);
    cudaFuncSetAttribute(combine_kernel,
        cudaFuncAttributeMaxDynamicSharedMemorySize, K3_SMEM_BYTES);

    proj_kernel<<<dim3(NT, 3, BB), 256, PROJ_SMEM_BYTES>>>(x, qw, kw, vw);
    flash_kernel<<<dim3(NT, JS, BB), 256, FL_SMEM_BYTES>>>();
    combine_kernel<<<dim3(NT, BB), 256, K3_SMEM_BYTES>>>(x, ow, out);
}

// round 16
// speedup vs baseline: 1.0293x; 1.0293x over previous
#include <cuda_runtime.h>
#include <cuda_pipeline.h>
#include <cstdint>

typedef unsigned long long u64;

#define BB 2
#define CC 256
#define RR 32
#define NN 6272
#define NT 49
#define JS 3

#define PS 68                  // O-staging row stride (floats)
#define KVBUF_U 3584           // u32 per KV buffer: kh1280 + kl1280 + vh1024
#define FL_SMEM_BYTES (8 * 16 * PS * 4)   // 34816; covers 2*KVBUF_U*4=28672

// ---------------- scratch ---------------------------------------------------
__device__ uint32_t g_qbh[BB][NN][16];  // q fp16-hi pairs (r=2u,2u+1), natural
__device__ uint32_t g_qbl[BB][NN][16];  // q fp16-lo pairs
__device__ uint32_t g_kbh[BB][NN][16];  // k fp16-hi pairs, slot-permuted
__device__ uint32_t g_kbl[BB][NN][16];
__device__ uint32_t g_vbh[BB][RR][NN/2]; // v fp16-hi pairs [r][perm j-pair]
__device__ float    g_op [BB*JS][RR][NN];
__device__ float    g_ll [BB*JS][NN];
__device__ float    g_mm [BB*JS][NN];

// ---------------- helpers ----------------------------------------------------
__device__ __forceinline__ u64 dup2(float a) {
    u64 r; asm("mov.b64 %0,{%1,%1};" : "=l"(r) : "f"(a)); return r;
}
__device__ __forceinline__ u64 ffma2(u64 a, u64 b, u64 c) {
    u64 d; asm("fma.rn.f32x2 %0,%1,%2,%3;" : "=l"(d) : "l"(a), "l"(b), "l"(c)); return d;
}
__device__ __forceinline__ void unpack2(u64 a, float& x, float& y) {
    asm("mov.b64 {%0,%1},%2;" : "=f"(x), "=f"(y) : "l"(a));
}
__device__ __forceinline__ float ex2(float x) {
    float y; asm("ex2.approx.f32 %0,%1;" : "=f"(y) : "f"(x)); return y;
}
// pack (v0,v1) to fp16x2 (low half = v0)
__device__ __forceinline__ uint32_t hfpack(float v0, float v1) {
    uint32_t r;
    asm("cvt.rn.f16x2.f32 %0, %1, %2;" : "=r"(r) : "f"(v1), "f"(v0));
    return r;
}
// split (v0,v1) into fp16x2 hi + fp16x2 residual-lo
__device__ __forceinline__ void hfsplit(float v0, float v1,
                                        uint32_t& hp, uint32_t& lp) {
    hp = hfpack(v0, v1);
    float h0, h1;
    asm("{.reg .b16 lo, hi;\n\t"
        "mov.b32 {lo, hi}, %2;\n\t"
        "cvt.f32.f16 %0, lo;\n\t"
        "cvt.f32.f16 %1, hi;}"
        : "=f"(h0), "=f"(h1) : "r"(hp));
    lp = hfpack(v0 - h0, v1 - h1);
}
__device__ __forceinline__ void mma16h(float* c, const uint32_t* a,
                                       uint32_t b0, uint32_t b1) {
    asm("mma.sync.aligned.m16n8k16.row.col.f32.f16.f16.f32 "
        "{%0,%1,%2,%3}, {%4,%5,%6,%7}, {%8,%9}, {%0,%1,%2,%3};"
        : "+f"(c[0]), "+f"(c[1]), "+f"(c[2]), "+f"(c[3])
        : "r"(a[0]), "r"(a[1]), "r"(a[2]), "r"(a[3]), "r"(b0), "r"(b1));
}

// ============================================================================
// Kernel 1: projection, one of {q,k,v} per block. grid (49, 3, 2), 256 thr.
// ============================================================================
#define PROJ_SMEM_FLOATS (8192 + 2 * 4096)
#define PROJ_SMEM_BYTES  (PROJ_SMEM_FLOATS * 4)   // 65536

__global__ void __launch_bounds__(256) proj_kernel(
    const float* __restrict__ x, const float* __restrict__ qw,
    const float* __restrict__ kw, const float* __restrict__ vw)
{
    extern __shared__ float sm[];
    float* ws = sm;           // [32][256] weights; reused as V staging
    float* xs = sm + 8192;    // 2 x [32][128]
    int tid = threadIdx.x, nt = blockIdx.x, which = blockIdx.y, b = blockIdx.z;
    const float* w = (which == 0) ? qw : (which == 1) ? kw : vw;
    const float* xb = x + (size_t)b * CC * NN + nt * 128;

    #pragma unroll
    for (int i = 0; i < 8; i++)
        __pipeline_memcpy_async(&ws[(tid + i * 256) * 4], &w[(tid + i * 256) * 4], 16);
    #pragma unroll
    for (int i = 0; i < 4; i++) {
        int lin4 = tid + i * 256;
        int cc = lin4 >> 5, nn4 = (lin4 & 31) * 4;
        __pipeline_memcpy_async(&xs[cc * 128 + nn4],
                                &xb[(size_t)cc * NN + nn4], 16);
    }
    __pipeline_commit();

    int tr = tid >> 5, tn = tid & 31;
    u64 acc[4][2];
    #pragma unroll
    for (int i = 0; i < 4; i++) { acc[i][0] = 0ull; acc[i][1] = 0ull; }

    #pragma unroll
    for (int ch = 0; ch < 8; ch++) {
        __pipeline_wait_prior(0);
        __syncthreads();
        if (ch + 1 < 8) {
            float* xd = xs + ((ch + 1) & 1) * 4096;
            int c0n = (ch + 1) * 32;
            #pragma unroll
            for (int i = 0; i < 4; i++) {
                int lin4 = tid + i * 256;
                int cc = lin4 >> 5, nn4 = (lin4 & 31) * 4;
                __pipeline_memcpy_async(&xd[cc * 128 + nn4],
                                        &xb[(size_t)(c0n + cc) * NN + nn4], 16);
            }
            __pipeline_commit();
        }
        float* xc = xs + (ch & 1) * 4096;
        int c0 = ch * 32;
        #pragma unroll 8
        for (int cc = 0; cc < 32; cc++) {
            ulonglong2 xv = *(ulonglong2*)&xc[cc * 128 + tn * 4];
            #pragma unroll
            for (int rr = 0; rr < 4; rr++) {
                u64 wv = dup2(ws[(tr * 4 + rr) * 256 + c0 + cc]);
                acc[rr][0] = ffma2(wv, xv.x, acc[rr][0]);
                acc[rr][1] = ffma2(wv, xv.y, acc[rr][1]);
            }
        }
    }

    const float qscale = 0.17677669529663687f * 1.4426950408889634f;
    int n0 = nt * 128 + tn * 4, r0 = tr * 4;
    float vals[4][4];   // [rr][nn]
    #pragma unroll
    for (int rr = 0; rr < 4; rr++) {
        unpack2(acc[rr][0], vals[rr][0], vals[rr][1]);
        unpack2(acc[rr][1], vals[rr][2], vals[rr][3]);
    }

    if (which == 0) {
        #pragma unroll
        for (int nn = 0; nn < 4; nn++) {
            uint32_t hp0, lp0, hp1, lp1;
            hfsplit(vals[0][nn] * qscale, vals[1][nn] * qscale, hp0, lp0);
            hfsplit(vals[2][nn] * qscale, vals[3][nn] * qscale, hp1, lp1);
            *(uint2*)&g_qbh[b][n0 + nn][2 * tr] = make_uint2(hp0, hp1);
            *(uint2*)&g_qbl[b][n0 + nn][2 * tr] = make_uint2(lp0, lp1);
        }
    } else if (which == 1) {
        // K: slot-permuted: u -> p = kts*8 + 2*(w&3) + (w>>2)
        #pragma unroll
        for (int nn = 0; nn < 4; nn++) {
            #pragma unroll
            for (int pi = 0; pi < 2; pi++) {
                uint32_t hp, lp;
                hfsplit(vals[2 * pi][nn], vals[2 * pi + 1][nn], hp, lp);
                int u = 2 * tr + pi;
                int kts = u >> 3, ww = u & 7;
                int p = kts * 8 + 2 * (ww & 3) + (ww >> 2);
                g_kbh[b][n0 + nn][p] = hp;
                g_kbl[b][n0 + nn][p] = lp;
            }
        }
    } else {
        // V: fp16-hi pairs along j, permuted slot layout per 64-j tile.
        __syncthreads();
        uint32_t* st_h = (uint32_t*)ws;          // [32 r][64 u32]
        #pragma unroll
        for (int rr = 0; rr < 4; rr++) {
            #pragma unroll
            for (int pi = 0; pi < 2; pi++) {
                uint32_t hp = hfpack(vals[rr][2 * pi], vals[rr][2 * pi + 1]);
                int ulc = tn * 2 + pi;
                int tl = ulc >> 5, ul = ulc & 31;
                int kt = ul >> 3, ww = ul & 7;
                int idx = tl * 32 + 2 * (kt * 4 + (ww & 3)) + (ww >> 2);
                st_h[(r0 + rr) * 64 + idx] = hp;
            }
        }
        __syncthreads();
        #pragma unroll
        for (int i = 0; i < 2; i++) {
            int lin4 = tid + i * 256;
            int r = lin4 >> 4, c4 = (lin4 & 15) * 4;
            *(uint4*)&g_vbh[b][r][nt * 64 + c4] = *(uint4*)&st_h[r * 64 + c4];
        }
    }
}

// ============================================================================
// Kernel 2: flash. grid (49, 3, 2), 256 threads (8 warps).
// S: fp16 3-term (48 mma). Online per-row max; P = ex2(s - m) in (0,1]
// (fp16-safe). PV: fp16 P x fp16 V-hi (16 mma) + consistent l (4 ones-mma).
// O/l accumulators rescaled by ex2(m_old - m_new) per tile. 68 mma total.
// ============================================================================
__device__ __forceinline__ void load_kv(uint32_t* smbase, int buf, int b,
                                        int j0, int tid)
{
    uint32_t* kd = smbase + buf * KVBUF_U;
    uint32_t* kld = kd + 1280;
    uint32_t* vhd = kd + 2560;
    #pragma unroll
    for (int i = 0; i < 2; i++) {
        int c = tid + i * 256;              // 0..511
        int arr = c >> 8, cc = c & 255;
        int j = cc >> 2, uu = cc & 3;
        uint32_t* dst = (arr ? kld : kd) + j * 20 + uu * 4;
        const uint32_t* src = arr ? &g_kbl[b][j0 + j][uu * 4]
                                  : &g_kbh[b][j0 + j][uu * 4];
        __pipeline_memcpy_async(dst, src, 16);
    }
    {
        int jp0 = j0 >> 1;
        int c = tid;                        // 0..255
        int r = c >> 3, ch = c & 7;
        uint32_t off = (uint32_t)(r * 32 + ((4 * ch) ^ ((r & 3) << 3)));
        __pipeline_memcpy_async(&vhd[off], &g_vbh[b][r][jp0 + 4 * ch], 16);
    }
    __pipeline_commit();
}

__global__ void __launch_bounds__(256, 2) flash_kernel()
{
    extern __shared__ float sm[];
    uint32_t* smu = (uint32_t*)sm;
    int tid = threadIdx.x;
    int w = tid >> 5, ln = tid & 31;
    int g = ln >> 2, t = ln & 3;

    int it = blockIdx.x, spl = blockIdx.y, b = blockIdx.z;
    int i0 = it * 128;
    int jt0 = spl * 33;
    int njt = (spl < 2) ? 33 : 32;
    int iw = i0 + w * 16;

    load_kv(smu, 0, b, jt0 * 64, tid);

    uint32_t qAh[2][4], qAl[2][4];
    {
        const uint32_t* qh = &g_qbh[b][0][0];
        const uint32_t* ql = &g_qbl[b][0][0];
        #pragma unroll
        for (int kts = 0; kts < 2; kts++) {
            int cA = kts * 8 + t, cB = kts * 8 + t + 4;
            qAh[kts][0] = qh[(size_t)(iw + g) * 16 + cA];
            qAh[kts][1] = qh[(size_t)(iw + g + 8) * 16 + cA];
            qAh[kts][2] = qh[(size_t)(iw + g) * 16 + cB];
            qAh[kts][3] = qh[(size_t)(iw + g + 8) * 16 + cB];
            qAl[kts][0] = ql[(size_t)(iw + g) * 16 + cA];
            qAl[kts][1] = ql[(size_t)(iw + g + 8) * 16 + cA];
            qAl[kts][2] = ql[(size_t)(iw + g) * 16 + cB];
            qAl[kts][3] = ql[(size_t)(iw + g + 8) * 16 + cB];
        }
    }

    float oC[4][4];
    #pragma unroll
    for (int i = 0; i < 4; i++)
        #pragma unroll
        for (int j = 0; j < 4; j++) oC[i][j] = 0.0f;
    float oL[4] = {0.0f, 0.0f, 0.0f, 0.0f};
    float m_g = -1e30f, m_h = -1e30f;    // running row maxes (rows g, g+8)

    const uint32_t ONE2 = 0x3c003c00u;   // fp16x2 (1.0, 1.0)

    for (int jt = 0; jt < njt; jt++) {
        int buf = jt & 1;
        __pipeline_wait_prior(0);
        __syncthreads();
        if (jt + 1 < njt) load_kv(smu, buf ^ 1, b, (jt0 + jt + 1) * 64, tid);

        const uint32_t* khs = smu + buf * KVBUF_U;
        const uint32_t* kls = khs + 1280;
        const uint32_t* vhs = khs + 2560;

        // ---- S = Q K^T : fp16 3-term ----------------------------------------
        float sC[8][4];
        #pragma unroll
        for (int nt = 0; nt < 8; nt++)
            #pragma unroll
            for (int r = 0; r < 4; r++) sC[nt][r] = 0.0f;

        #pragma unroll
        for (int kts = 0; kts < 2; kts++)
            #pragma unroll
            for (int nt = 0; nt < 8; nt++) {
                int off = (nt * 8 + g) * 20 + 2 * (kts * 4 + t);
                uint2 hh = *(const uint2*)&khs[off];
                uint2 ll = *(const uint2*)&kls[off];
                mma16h(sC[nt], qAh[kts], hh.x, hh.y);
                mma16h(sC[nt], qAh[kts], ll.x, ll.y);
                mma16h(sC[nt], qAl[kts], hh.x, hh.y);
            }

        // ---- online per-row max + accumulator rescale ------------------------
        float tg = fmaxf(sC[0][0], sC[0][1]);
        float th = fmaxf(sC[0][2], sC[0][3]);
        #pragma unroll
        for (int nt = 1; nt < 8; nt++) {
            tg = fmaxf(tg, fmaxf(sC[nt][0], sC[nt][1]));
            th = fmaxf(th, fmaxf(sC[nt][2], sC[nt][3]));
        }
        tg = fmaxf(tg, __shfl_xor_sync(0xffffffffu, tg, 1));
        tg = fmaxf(tg, __shfl_xor_sync(0xffffffffu, tg, 2));
        th = fmaxf(th, __shfl_xor_sync(0xffffffffu, th, 1));
        th = fmaxf(th, __shfl_xor_sync(0xffffffffu, th, 2));
        float mng = fmaxf(m_g, tg), mnh = fmaxf(m_h, th);
        float crg = ex2(m_g - mng), crh = ex2(m_h - mnh);
        m_g = mng; m_h = mnh;
        #pragma unroll
        for (int nt2 = 0; nt2 < 4; nt2++) {
            oC[nt2][0] *= crg; oC[nt2][1] *= crg;
            oC[nt2][2] *= crh; oC[nt2][3] *= crh;
        }
        oL[0] *= crg; oL[1] *= crg; oL[2] *= crh; oL[3] *= crh;

        // ---- softmax + PV per kt ---------------------------------------------
        #pragma unroll
        for (int kt = 0; kt < 4; kt++) {
            float e0 = ex2(sC[2 * kt][0] - m_g);
            float e1 = ex2(sC[2 * kt][1] - m_g);
            float e2 = ex2(sC[2 * kt][2] - m_h);
            float e3 = ex2(sC[2 * kt][3] - m_h);
            float e4 = ex2(sC[2 * kt + 1][0] - m_g);
            float e5 = ex2(sC[2 * kt + 1][1] - m_g);
            float e6 = ex2(sC[2 * kt + 1][2] - m_h);
            float e7 = ex2(sC[2 * kt + 1][3] - m_h);
            uint32_t pA[4];
            pA[0] = hfpack(e0, e1);
            pA[1] = hfpack(e2, e3);
            pA[2] = hfpack(e4, e5);
            pA[3] = hfpack(e6, e7);
            #pragma unroll
            for (int nt2 = 0; nt2 < 4; nt2++) {
                int r = nt2 * 8 + g;
                uint32_t off = (uint32_t)(r * 32 +
                               2 * ((kt * 4 + t) ^ ((r & 3) << 2)));
                uint2 vh2 = *(const uint2*)&vhs[off];
                mma16h(oC[nt2], pA, vh2.x, vh2.y);
            }
            mma16h(oL, pA, ONE2, ONE2);
        }
    }

    // ---- epilogue: O staging aliases the dead KV buffers --------------------
    __syncthreads();      // all warps done reading KV smem
    int bs = b * JS + spl;
    float* pw = sm + w * (16 * PS);
    #pragma unroll
    for (int nt = 0; nt < 4; nt++) {
        *(float2*)&pw[g * PS + nt * 8 + 2 * t]       = make_float2(oC[nt][0], oC[nt][1]);
        *(float2*)&pw[(g + 8) * PS + nt * 8 + 2 * t] = make_float2(oC[nt][2], oC[nt][3]);
    }
    if (t == 0) {
        g_ll[bs][iw + g]     = oL[0];
        g_ll[bs][iw + g + 8] = oL[2];
        g_mm[bs][iw + g]     = m_g;
        g_mm[bs][iw + g + 8] = m_h;
    }
    __syncthreads();
    #pragma unroll
    for (int i = 0; i < 16; i++) {
        int idx = tid + i * 256;          // 0..4095
        int r = idx >> 7, ii = idx & 127;
        int w2 = ii >> 4, il = ii & 15;
        g_op[bs][r][i0 + ii] = sm[w2 * (16 * PS) + il * PS + r];
    }
}

// ============================================================================
// Kernel 3: split combine (m/l-weighted) + output projection + residual.
// grid (49, 2)
// ============================================================================
#define K3_SMEM_FLOATS (4096 + 8192 + 384 + 32768)
#define K3_SMEM_BYTES  (K3_SMEM_FLOATS * 4)

__global__ void __launch_bounds__(256) combine_kernel(
    const float* __restrict__ x, const float* __restrict__ ow,
    float* __restrict__ out)
{
    extern __shared__ float sm[];
    float* oc  = sm;            // [32][128]
    float* ows = sm + 4096;     // [256][32]
    float* wsc = sm + 12288;    // [3][128]
    float* os  = sm + 12672;    // [256][128]

    int tid = threadIdx.x, nt = blockIdx.x, b = blockIdx.y;
    int n0 = nt * 128;

    #pragma unroll
    for (int i = 0; i < 8; i++) {
        int lin4 = tid + i * 256;
        *(float4*)&ows[lin4 * 4] = *(const float4*)&ow[lin4 * 4];
    }
    if (tid < 128) {
        int n = n0 + tid;
        float m0 = g_mm[b*3+0][n], m1 = g_mm[b*3+1][n], m2 = g_mm[b*3+2][n];
        float ms = fmaxf(m0, fmaxf(m1, m2));
        float w0 = ex2(m0 - ms), w1 = ex2(m1 - ms), w2 = ex2(m2 - ms);
        float ls = g_ll[b*3+0][n]*w0 + g_ll[b*3+1][n]*w1 + g_ll[b*3+2][n]*w2;
        float inv = 1.0f / ls;
        wsc[tid]       = w0 * inv;
        wsc[128 + tid] = w1 * inv;
        wsc[256 + tid] = w2 * inv;
    }
    __syncthreads();

    #pragma unroll
    for (int i = 0; i < 16; i++) {
        int idx = tid + i * 256;
        int r = idx >> 7, n = idx & 127;
        oc[idx] = g_op[b*3+0][r][n0+n] * wsc[n]
                + g_op[b*3+1][r][n0+n] * wsc[128+n]
                + g_op[b*3+2][r][n0+n] * wsc[256+n];
    }
    __syncthreads();

    {
        u64 wd[32];
        #pragma unroll
        for (int r = 0; r < 32; r++) wd[r] = dup2(ows[tid * 32 + r]);
        #pragma unroll 2
        for (int np = 0; np < 64; np++) {
            u64 acc = 0ull;
            #pragma unroll
            for (int r = 0; r < 32; r++)
                acc = ffma2(wd[r], *(u64*)&oc[r * 128 + np * 2], acc);
            *(u64*)&os[tid * 128 + np * 2] = acc;
        }
    }
    __syncthreads();

    const float* xb = x + (size_t)b * CC * NN;
    float* ob = out + (size_t)b * CC * NN;
    #pragma unroll
    for (int i = 0; i < 32; i++) {
        int lin4 = tid + i * 256;
        int c = lin4 >> 5, n4 = (lin4 & 31) * 4;
        float4 xv = *(const float4*)&xb[(size_t)c * NN + n0 + n4];
        float4 ov = *(float4*)&os[c * 128 + n4];
        *(float4*)&ob[(size_t)c * NN + n0 + n4] =
            make_float4(xv.x + ov.x, xv.y + ov.y, xv.z + ov.z, xv.w + ov.w);
    }
}

// ============================================================================
extern "C" void kernel_launch(void* const* d_in, const int* in_sizes, int n_in,
                              void* d_out, int out_size)
{
    const float* x  = (const float*)d_in[0];
    const float* qw = (const float*)d_in[1];
    const float* kw = (const float*)d_in[2];
    const float* vw = (const float*)d_in[3];
    const float* ow = (const float*)d_in[4];
    float* out = (float*)d_out;

    cudaFuncSetAttribute(proj_kernel,
        cudaFuncAttributeMaxDynamicSharedMemorySize, PROJ_SMEM_BYTES);
    cudaFuncSetAttribute(flash_kernel,
        cudaFuncAttributeMaxDynamicSharedMemorySize, FL_SMEM_BYTES);
    cudaFuncSetAttribute(combine_kernel,
        cudaFuncAttributeMaxDynamicSharedMemorySize, K3_SMEM_BYTES);

    proj_kernel<<<dim3(NT, 3, BB), 256, PROJ_SMEM_BYTES>>>(x, qw, kw, vw);
    flash_kernel<<<dim3(NT, JS, BB), 256, FL_SMEM_BYTES>>>();
    combine_kernel<<<dim3(NT, BB), 256, K3_SMEM_BYTES>>>(x, ow, out);
}